// round 6
// baseline (speedup 1.0000x reference)
#include <cuda_runtime.h>
#include <math.h>

// ---------------- problem constants ----------------
#define HP    256
#define WPIX  512
#define P_IMG 131072          // HP*WPIX  (low-res pixels)
#define NPTS  1179648         // P_IMG*9  (splat points)
#define H_OUT 512
#define W_OUT 1024
#define HW    524288          // H_OUT*W_OUT
#define C_IN  128
#define C_OUT 64
#define VB    75497472        // NPTS*64  (vals2 elements per batch)
#define MAXREC 24

// ---------------- device scratch (allocation-free) ----------------
__device__ float g_vals2[2 * VB];                  // [b][p*9+tap][64]
__device__ int2  g_rec[(size_t)HW * MAXREC];       // splat record table
__device__ int   g_cnt[HW];
__device__ float g_ws[2 * 576 * 128];              // folded weights, row m = tap*64+o
__device__ float g_vbias[2 * 576];
__device__ float g_bias2[64];
__device__ float g_gn1sum[64];                     // [b][32 groups]
__device__ float g_gn1ssq[64];
__device__ float g_gn2sum[128];                    // [b][64 ch]
__device__ float g_gn2ssq[128];

// ---------------- K0: zero counters/stats ----------------
__global__ void k_zero() {
    int i = blockIdx.x * 256 + threadIdx.x;
    if (i < HW) g_cnt[i] = 0;
    if (i < 64)  { g_gn1sum[i] = 0.f; g_gn1ssq[i] = 0.f; }
    if (i < 128) { g_gn2sum[i] = 0.f; g_gn2ssq[i] = 0.f; }
}

// ---------------- K1: GroupNorm-1 stats ----------------
__global__ __launch_bounds__(256) void k_gn1(const float* __restrict__ x) {
    int bc = blockIdx.x;                 // b*128 + c
    const float4* p = (const float4*)(x + (size_t)bc * P_IMG + (size_t)blockIdx.y * 32768);
    float s = 0.f, q = 0.f;
    for (int i = threadIdx.x; i < 8192; i += 256) {
        float4 v = p[i];
        s += v.x + v.y + v.z + v.w;
        q += v.x * v.x + v.y * v.y + v.z * v.z + v.w * v.w;
    }
    __shared__ float sh1[8], sh2[8];
    for (int off = 16; off; off >>= 1) {
        s += __shfl_down_sync(0xffffffffu, s, off);
        q += __shfl_down_sync(0xffffffffu, q, off);
    }
    int lane = threadIdx.x & 31, warp = threadIdx.x >> 5;
    if (lane == 0) { sh1[warp] = s; sh2[warp] = q; }
    __syncthreads();
    if (threadIdx.x == 0) {
        float S = 0.f, Q = 0.f;
        for (int i = 0; i < 8; i++) { S += sh1[i]; Q += sh2[i]; }
        int b = bc >> 7, g = (bc & 127) >> 2;     // 4 channels per group
        atomicAdd(&g_gn1sum[b * 32 + g], S);
        atomicAdd(&g_gn1ssq[b * 32 + g], Q);
    }
}

// ---------------- K2: fold w_post . w_conv . GN1 into ws/vbias/bias2 -------
__global__ __launch_bounds__(128) void k_prep(const float* __restrict__ w_conv,
                                              const float* __restrict__ w_post,
                                              const float* __restrict__ gamma1,
                                              const float* __restrict__ beta1,
                                              const float* __restrict__ splat_bias,
                                              const float* __restrict__ b_post) {
    int m = blockIdx.x;                  // tap-major row: m = tap*64 + o
    int tap = m >> 6, o = m & 63;
    int c = threadIdx.x;                 // 0..127
    __shared__ float sp[64];
    __shared__ float red[128];
    if (c < 64) sp[c] = w_post[o * 64 + c];
    __syncthreads();
    float w2 = 0.f;
    #pragma unroll 8
    for (int k = 0; k < 64; k++) w2 += sp[k] * w_conv[(k * 9 + tap) * 128 + c];

    float ga = gamma1[c], be = beta1[c];
    int g = c >> 2;
    for (int b = 0; b < 2; b++) {
        float su = g_gn1sum[b * 32 + g], sq = g_gn1ssq[b * 32 + g];
        float mu  = su * (1.0f / 524288.0f);
        float var = sq * (1.0f / 524288.0f) - mu * mu;
        float rs  = rsqrtf(var + 1e-5f);
        float sc  = rs * ga;
        float sh  = be - mu * sc;
        g_ws[((size_t)b * 576 + m) * 128 + c] = w2 * sc;
        red[c] = w2 * sh;
        __syncthreads();
        for (int s = 64; s > 0; s >>= 1) { if (c < s) red[c] += red[c + s]; __syncthreads(); }
        if (c == 0) g_vbias[b * 576 + m] = red[0];
        __syncthreads();
    }
    if (tap == 0) {
        red[c] = (c < 64) ? sp[c] * splat_bias[c] : 0.f;
        __syncthreads();
        for (int s = 64; s > 0; s >>= 1) { if (c < s) red[c] += red[c + s]; __syncthreads(); }
        if (c == 0) g_bias2[o] = red[0] + b_post[o];
    }
}

// ---------------- K3: GEMM  vals2[b][p*9+tap][o] = ws @ x + vbias ----------
// C = W(64x128) @ X(128x128px) per (tap, pixel-tile, batch)
__global__ __launch_bounds__(256) void k_gemm(const float* __restrict__ x) {
    int b = blockIdx.z, tap = blockIdx.y;
    int pbase = blockIdx.x * 128;
    int tid = threadIdx.x;
    int ty = tid >> 4;                   // 0..15  -> m micro (4)
    int tx = tid & 15;                   // 0..15  -> n micro (8)

    __shared__ float As[64][33];         // [m][k], padded
    __shared__ float Bs[32][128];        // [k][n]

    const float* wsb = g_ws + ((size_t)b * 576 + tap * 64) * 128;
    const float* xb  = x + (size_t)b * C_IN * P_IMG;

    float4 acc[8];
    #pragma unroll
    for (int j = 0; j < 8; j++) acc[j] = make_float4(0.f, 0.f, 0.f, 0.f);

    for (int kc = 0; kc < 128; kc += 32) {
        // load A chunk: 64 rows x 32 cols (512 float4, 2 per thread)
        #pragma unroll
        for (int i = 0; i < 2; i++) {
            int idx = tid + i * 256;
            int row = idx >> 3, c4 = idx & 7;
            float4 wv = *(const float4*)(wsb + row * 128 + kc + c4 * 4);
            float* ar = &As[row][c4 * 4];
            ar[0] = wv.x; ar[1] = wv.y; ar[2] = wv.z; ar[3] = wv.w;
        }
        // load X chunk: 32 rows x 128 cols (1024 float4, 4 per thread)
        #pragma unroll
        for (int i = 0; i < 4; i++) {
            int idx = tid + i * 256;
            int r = idx >> 5, c4 = idx & 31;
            float4 xv = *(const float4*)(xb + (size_t)(kc + r) * P_IMG + pbase + c4 * 4);
            ((float4*)&Bs[r][0])[c4] = xv;
        }
        __syncthreads();
        #pragma unroll
        for (int kk = 0; kk < 32; kk++) {
            float a0 = As[ty * 4 + 0][kk];
            float a1 = As[ty * 4 + 1][kk];
            float a2 = As[ty * 4 + 2][kk];
            float a3 = As[ty * 4 + 3][kk];
            float4 b0 = *(const float4*)&Bs[kk][tx * 8];
            float4 b1 = *(const float4*)&Bs[kk][tx * 8 + 4];
            float bb[8] = {b0.x, b0.y, b0.z, b0.w, b1.x, b1.y, b1.z, b1.w};
            #pragma unroll
            for (int j = 0; j < 8; j++) {
                acc[j].x += a0 * bb[j];
                acc[j].y += a1 * bb[j];
                acc[j].z += a2 * bb[j];
                acc[j].w += a3 * bb[j];
            }
        }
        __syncthreads();
    }

    float4 vb = *(const float4*)&g_vbias[b * 576 + tap * 64 + ty * 4];
    #pragma unroll
    for (int j = 0; j < 8; j++) {
        int p = pbase + tx * 8 + j;
        float4 o = acc[j];
        o.x += vb.x; o.y += vb.y; o.z += vb.z; o.w += vb.w;
        *(float4*)&g_vals2[((size_t)b * NPTS + (size_t)p * 9 + tap) * 64 + ty * 4] = o;
    }
}

// ---------------- K4: build splat record table ----------------
__device__ __forceinline__ void emit_rec(int m, float wt, int yi, int xi) {
    if (yi < 0)          { yi = -yi;        xi = (xi + 512) & 1023; }
    else if (yi >= 512)  { yi = 1024 - yi;  xi = (xi + 512) & 1023; }
    if (yi > 511) yi = 511;
    if (yi < 0)   yi = 0;
    int idx = yi * 1024 + xi;
    int slot = atomicAdd(&g_cnt[idx], 1);
    if (slot < MAXREC) g_rec[(size_t)idx * MAXREC + slot] = make_int2(m, __float_as_int(wt));
}

__global__ __launch_bounds__(256) void k_build(const float* __restrict__ grid) {
    int m = blockIdx.x * 256 + threadIdx.x;
    if (m >= NPTS) return;
    float2 gxy = ((const float2*)grid)[m];
    float px = (gxy.x + 1.0f) * 0.5f * 1023.0f;
    float py = (gxy.y + 1.0f) * 0.5f * 511.0f;
    float fpx = floorf(px), fpy = floorf(py);
    int x0 = (int)fpx, y0 = (int)fpy;
    float fx = px - fpx, fy = py - fpy;
    float wx0 = 1.0f - fx, wy0 = 1.0f - fy;
    int x0w = x0 & 1023, x1w = (x0 + 1) & 1023;
    emit_rec(m, wx0 * wy0, y0,     x0w);
    emit_rec(m, wx0 * fy,  y0 + 1, x0w);
    emit_rec(m, fx  * wy0, y0,     x1w);
    emit_rec(m, fx  * fy,  y0 + 1, x1w);
}

// ---------------- K5: gather + div + bias + GN2 stats ----------------
__global__ __launch_bounds__(256) void k_gather(float* __restrict__ out) {
    int b = blockIdx.y;
    int base = blockIdx.x * 256;         // 256 pixels per block
    int tid = threadIdx.x;
    int w = tid >> 5, lane = tid & 31;
    __shared__ float buf[64][33];
    float sums[8], ssqs[8];
    #pragma unroll
    for (int r = 0; r < 8; r++) { sums[r] = 0.f; ssqs[r] = 0.f; }

    const float* vbase = g_vals2 + (size_t)b * VB;

    for (int t = 0; t < 8; t++) {
        int pb = base + t * 32;
        for (int jj = 0; jj < 4; jj++) {
            int pp = jj * 8 + w;
            int p = pb + pp;
            int cnt = g_cnt[p];
            if (cnt > MAXREC) cnt = MAXREC;
            float a0 = 0.f, a1 = 0.f, den = 0.f;
            const int2* rp = &g_rec[(size_t)p * MAXREC];
            for (int r = 0; r < cnt; r++) {
                int2 rec = rp[r];
                float wt = __int_as_float(rec.y);
                const float* v = vbase + (size_t)rec.x * 64;
                a0 += wt * v[lane];
                a1 += wt * v[lane + 32];
                den += wt;
            }
            float rd = 1.0f / fmaxf(den, 1e-8f);
            buf[lane][pp]      = a0 * rd + g_bias2[lane];
            buf[lane + 32][pp] = a1 * rd + g_bias2[lane + 32];
        }
        __syncthreads();
        #pragma unroll
        for (int r = 0; r < 8; r++) {
            int c = r * 8 + w;
            float v = buf[c][lane];
            out[((size_t)(b * 64 + c)) * HW + pb + lane] = v;
            sums[r] += v; ssqs[r] += v * v;
        }
        __syncthreads();
    }
    #pragma unroll
    for (int r = 0; r < 8; r++) {
        float s = sums[r], q = ssqs[r];
        for (int off = 16; off; off >>= 1) {
            s += __shfl_down_sync(0xffffffffu, s, off);
            q += __shfl_down_sync(0xffffffffu, q, off);
        }
        if (lane == 0) {
            atomicAdd(&g_gn2sum[b * 64 + r * 8 + w], s);
            atomicAdd(&g_gn2ssq[b * 64 + r * 8 + w], q);
        }
    }
}

// ---------------- K6: GN2 + exact GELU ----------------
__global__ __launch_bounds__(256) void k_final(float* __restrict__ out,
                                               const float* __restrict__ gamma2,
                                               const float* __restrict__ beta2) {
    size_t i4 = (size_t)blockIdx.x * 256 + threadIdx.x;   // float4 index
    int bc = (int)(i4 >> 17);            // 131072 float4 per (b,c) row
    int b = bc >> 6, c = bc & 63;
    int g = c >> 1;                      // 2 channels per group
    float S = g_gn2sum[b * 64 + 2 * g] + g_gn2sum[b * 64 + 2 * g + 1];
    float Q = g_gn2ssq[b * 64 + 2 * g] + g_gn2ssq[b * 64 + 2 * g + 1];
    float mu  = S * (1.0f / 1048576.0f);
    float var = Q * (1.0f / 1048576.0f) - mu * mu;
    float sc = rsqrtf(var + 1e-5f) * gamma2[c];
    float sh = beta2[c] - mu * sc;
    float4 v = ((float4*)out)[i4];
    float t;
    t = v.x * sc + sh; v.x = 0.5f * t * (1.0f + erff(t * 0.70710678f));
    t = v.y * sc + sh; v.y = 0.5f * t * (1.0f + erff(t * 0.70710678f));
    t = v.z * sc + sh; v.z = 0.5f * t * (1.0f + erff(t * 0.70710678f));
    t = v.w * sc + sh; v.w = 0.5f * t * (1.0f + erff(t * 0.70710678f));
    ((float4*)out)[i4] = v;
}

// ---------------- launch ----------------
extern "C" void kernel_launch(void* const* d_in, const int* in_sizes, int n_in,
                              void* d_out, int out_size) {
    const float* x          = (const float*)d_in[0];
    const float* grid       = (const float*)d_in[1];
    const float* gamma1     = (const float*)d_in[2];
    const float* beta1      = (const float*)d_in[3];
    const float* w_conv     = (const float*)d_in[4];
    const float* splat_bias = (const float*)d_in[5];
    const float* w_post     = (const float*)d_in[6];
    const float* b_post     = (const float*)d_in[7];
    const float* gamma2     = (const float*)d_in[8];
    const float* beta2      = (const float*)d_in[9];
    float* out = (float*)d_out;

    k_zero<<<2048, 256>>>();
    k_gn1<<<dim3(256, 4), 256>>>(x);
    k_prep<<<576, 128>>>(w_conv, w_post, gamma1, beta1, splat_bias, b_post);
    k_gemm<<<dim3(1024, 9, 2), 256>>>(x);
    k_build<<<4608, 256>>>(grid);
    k_gather<<<dim3(2048, 2), 256>>>(out);
    k_final<<<65536, 256>>>(out, gamma2, beta2);
}

// round 8
// speedup vs baseline: 1.5970x; 1.5970x over previous
#include <cuda_runtime.h>
#include <cuda_bf16.h>
#include <cstdint>
#include <stdint.h>
#include <math.h>

// ---------------- problem constants ----------------
#define HP    256
#define WPIX  512
#define P_IMG 131072          // HP*WPIX  (low-res pixels)
#define NPTS  1179648         // P_IMG*9  (splat points)
#define H_OUT 512
#define W_OUT 1024
#define HW    524288          // H_OUT*W_OUT
#define C_IN  128
#define C_OUT 64
#define VB    75497472        // NPTS*64  (vals2 elements per batch)
#define MAXREC 24

// ---------------- device scratch (allocation-free) ----------------
__device__ float g_vals2[2 * VB];                  // [b][p*9+tap][64]
__device__ int2  g_rec[(size_t)HW * MAXREC];       // splat record table
__device__ int   g_cnt[HW];
__device__ __nv_bfloat16 g_wh[2 * 576 * 128];      // folded weights hi (row m = tap*64+o)
__device__ __nv_bfloat16 g_wl[2 * 576 * 128];      // folded weights lo
__device__ __nv_bfloat16 g_xh[(size_t)2 * C_IN * P_IMG];  // x split hi
__device__ __nv_bfloat16 g_xl[(size_t)2 * C_IN * P_IMG];  // x split lo
__device__ float g_vbias[2 * 576];
__device__ float g_bias2[64];
__device__ float g_gn1sum[64];                     // [b][32 groups]
__device__ float g_gn1ssq[64];
__device__ float g_gn2sum[128];                    // [b][64 ch]
__device__ float g_gn2ssq[128];

// ---------------- K0: zero counters/stats ----------------
__global__ void k_zero() {
    int i = blockIdx.x * 256 + threadIdx.x;
    if (i < HW) g_cnt[i] = 0;
    if (i < 64)  { g_gn1sum[i] = 0.f; g_gn1ssq[i] = 0.f; }
    if (i < 128) { g_gn2sum[i] = 0.f; g_gn2ssq[i] = 0.f; }
}

// ---------------- K1: GroupNorm-1 stats ----------------
__global__ __launch_bounds__(256) void k_gn1(const float* __restrict__ x) {
    int bc = blockIdx.x;                 // b*128 + c
    const float4* p = (const float4*)(x + (size_t)bc * P_IMG + (size_t)blockIdx.y * 32768);
    float s = 0.f, q = 0.f;
    for (int i = threadIdx.x; i < 8192; i += 256) {
        float4 v = p[i];
        s += v.x + v.y + v.z + v.w;
        q += v.x * v.x + v.y * v.y + v.z * v.z + v.w * v.w;
    }
    __shared__ float sh1[8], sh2[8];
    for (int off = 16; off; off >>= 1) {
        s += __shfl_down_sync(0xffffffffu, s, off);
        q += __shfl_down_sync(0xffffffffu, q, off);
    }
    int lane = threadIdx.x & 31, warp = threadIdx.x >> 5;
    if (lane == 0) { sh1[warp] = s; sh2[warp] = q; }
    __syncthreads();
    if (threadIdx.x == 0) {
        float S = 0.f, Q = 0.f;
        for (int i = 0; i < 8; i++) { S += sh1[i]; Q += sh2[i]; }
        int b = bc >> 7, g = (bc & 127) >> 2;     // 4 channels per group
        atomicAdd(&g_gn1sum[b * 32 + g], S);
        atomicAdd(&g_gn1ssq[b * 32 + g], Q);
    }
}

// ---------------- K1b: split x into bf16 hi/lo ----------------
__global__ __launch_bounds__(256) void k_split(const float* __restrict__ x) {
    size_t i = (size_t)blockIdx.x * 256 + threadIdx.x;   // float4 index
    float4 v = ((const float4*)x)[i];
    __nv_bfloat16 hx = __float2bfloat16(v.x);
    __nv_bfloat16 hy = __float2bfloat16(v.y);
    __nv_bfloat16 hz = __float2bfloat16(v.z);
    __nv_bfloat16 hw = __float2bfloat16(v.w);
    __nv_bfloat16 lx = __float2bfloat16(v.x - __bfloat162float(hx));
    __nv_bfloat16 ly = __float2bfloat16(v.y - __bfloat162float(hy));
    __nv_bfloat16 lz = __float2bfloat16(v.z - __bfloat162float(hz));
    __nv_bfloat16 lw = __float2bfloat16(v.w - __bfloat162float(hw));
    ((__nv_bfloat162*)g_xh)[2 * i]     = __halves2bfloat162(hx, hy);
    ((__nv_bfloat162*)g_xh)[2 * i + 1] = __halves2bfloat162(hz, hw);
    ((__nv_bfloat162*)g_xl)[2 * i]     = __halves2bfloat162(lx, ly);
    ((__nv_bfloat162*)g_xl)[2 * i + 1] = __halves2bfloat162(lz, lw);
}

// ---------------- K2: fold w_post . w_conv . GN1 into wh/wl/vbias/bias2 ----
__global__ __launch_bounds__(128) void k_prep(const float* __restrict__ w_conv,
                                              const float* __restrict__ w_post,
                                              const float* __restrict__ gamma1,
                                              const float* __restrict__ beta1,
                                              const float* __restrict__ splat_bias,
                                              const float* __restrict__ b_post) {
    int m = blockIdx.x;                  // tap-major row: m = tap*64 + o
    int tap = m >> 6, o = m & 63;
    int c = threadIdx.x;                 // 0..127
    __shared__ float sp[64];
    __shared__ float red[128];
    if (c < 64) sp[c] = w_post[o * 64 + c];
    __syncthreads();
    float w2 = 0.f;
    #pragma unroll 8
    for (int k = 0; k < 64; k++) w2 += sp[k] * w_conv[(k * 9 + tap) * 128 + c];

    float ga = gamma1[c], be = beta1[c];
    int g = c >> 2;
    for (int b = 0; b < 2; b++) {
        float su = g_gn1sum[b * 32 + g], sq = g_gn1ssq[b * 32 + g];
        float mu  = su * (1.0f / 524288.0f);
        float var = sq * (1.0f / 524288.0f) - mu * mu;
        float rs  = rsqrtf(var + 1e-5f);
        float sc  = rs * ga;
        float sh  = be - mu * sc;
        float wsv = w2 * sc;
        __nv_bfloat16 h = __float2bfloat16(wsv);
        g_wh[((size_t)b * 576 + m) * 128 + c] = h;
        g_wl[((size_t)b * 576 + m) * 128 + c] =
            __float2bfloat16(wsv - __bfloat162float(h));
        red[c] = w2 * sh;
        __syncthreads();
        for (int s = 64; s > 0; s >>= 1) { if (c < s) red[c] += red[c + s]; __syncthreads(); }
        if (c == 0) g_vbias[b * 576 + m] = red[0];
        __syncthreads();
    }
    if (tap == 0) {
        red[c] = (c < 64) ? sp[c] * splat_bias[c] : 0.f;
        __syncthreads();
        for (int s = 64; s > 0; s >>= 1) { if (c < s) red[c] += red[c + s]; __syncthreads(); }
        if (c == 0) g_bias2[o] = red[0] + b_post[o];
    }
}

// ---------------- tensor-core helpers ----------------
__device__ __forceinline__ void ldsm_x4(uint32_t* r, const void* p) {
    uint32_t a = (uint32_t)__cvta_generic_to_shared(p);
    asm volatile("ldmatrix.sync.aligned.m8n8.x4.shared.b16 {%0,%1,%2,%3}, [%4];"
        : "=r"(r[0]), "=r"(r[1]), "=r"(r[2]), "=r"(r[3]) : "r"(a));
}
__device__ __forceinline__ void ldsm_x2t(uint32_t& r0, uint32_t& r1, const void* p) {
    uint32_t a = (uint32_t)__cvta_generic_to_shared(p);
    asm volatile("ldmatrix.sync.aligned.m8n8.x2.trans.shared.b16 {%0,%1}, [%2];"
        : "=r"(r0), "=r"(r1) : "r"(a));
}
__device__ __forceinline__ void mma_bf16(float* c, const uint32_t* a,
                                         uint32_t b0, uint32_t b1) {
    asm volatile("mma.sync.aligned.m16n8k16.row.col.f32.bf16.bf16.f32 "
        "{%0,%1,%2,%3}, {%4,%5,%6,%7}, {%8,%9}, {%0,%1,%2,%3};"
        : "+f"(c[0]), "+f"(c[1]), "+f"(c[2]), "+f"(c[3])
        : "r"(a[0]), "r"(a[1]), "r"(a[2]), "r"(a[3]), "r"(b0), "r"(b1));
}

// ---------------- K3: tensor-core GEMM (split bf16, 3-term) ----------------
// Block: tap (64 m-rows) x 256 pixels.  grid = (9 taps, 512 n-tiles, 2 b)
// 8 warps = 2 (m) x 4 (n); warp tile 32m x 64n; mma m16n8k16.
__global__ __launch_bounds__(256) void k_gemm() {
    const int b = blockIdx.z, tap = blockIdx.x;
    const int pbase = blockIdx.y * 256;
    const int tid = threadIdx.x;
    const int warp = tid >> 5, lane = tid & 31;
    const int wm = warp >> 2, wn = warp & 3;
    const int g = lane >> 2, t = lane & 3;

    __shared__ __nv_bfloat16 Ah[64][24], Al[64][24];     // k-chunk 16 (+pad)
    __shared__ __nv_bfloat16 Bh[16][264], Bl[16][264];   // 256 n (+pad)

    float acc[2][8][4];
    #pragma unroll
    for (int i = 0; i < 2; i++)
        #pragma unroll
        for (int j = 0; j < 8; j++)
            #pragma unroll
            for (int k = 0; k < 4; k++) acc[i][j][k] = 0.f;

    const __nv_bfloat16* wh = g_wh + ((size_t)(b * 576 + tap * 64)) * 128;
    const __nv_bfloat16* wl = g_wl + ((size_t)(b * 576 + tap * 64)) * 128;
    const __nv_bfloat16* xh = g_xh + (size_t)b * C_IN * P_IMG;
    const __nv_bfloat16* xl = g_xl + (size_t)b * C_IN * P_IMG;

    const int a_row = lane & 15;                 // 0..15
    const int a_col = (lane & 16) ? 8 : 0;
    const int b_row = lane & 15;

    for (int kc = 0; kc < 128; kc += 16) {
        {   // A fill: 64 x 16 bf16, hi (tid<128) and lo (tid>=128)
            int half = tid >> 7;
            int m = (tid & 127) >> 1;
            int part = tid & 1;
            const __nv_bfloat16* src = (half ? wl : wh) + m * 128 + kc + part * 8;
            __nv_bfloat16* dst = half ? &Al[m][part * 8] : &Ah[m][part * 8];
            *(uint4*)dst = *(const uint4*)src;
        }
        {   // B fill: 16 x 256 bf16, hi + lo
            int r = tid >> 4, c16 = tid & 15;
            size_t off = (size_t)(kc + r) * P_IMG + pbase + c16 * 16;
            *(uint4*)&Bh[r][c16 * 16]     = *(const uint4*)(xh + off);
            *(uint4*)&Bh[r][c16 * 16 + 8] = *(const uint4*)(xh + off + 8);
            *(uint4*)&Bl[r][c16 * 16]     = *(const uint4*)(xl + off);
            *(uint4*)&Bl[r][c16 * 16 + 8] = *(const uint4*)(xl + off + 8);
        }
        __syncthreads();

        uint32_t ah[2][4], al[2][4];
        #pragma unroll
        for (int mt = 0; mt < 2; mt++) {
            ldsm_x4(ah[mt], &Ah[wm * 32 + mt * 16 + a_row][a_col]);
            ldsm_x4(al[mt], &Al[wm * 32 + mt * 16 + a_row][a_col]);
        }
        #pragma unroll
        for (int nt = 0; nt < 8; nt++) {
            uint32_t bh0, bh1, bl0, bl1;
            ldsm_x2t(bh0, bh1, &Bh[b_row][wn * 64 + nt * 8]);
            ldsm_x2t(bl0, bl1, &Bl[b_row][wn * 64 + nt * 8]);
            #pragma unroll
            for (int mt = 0; mt < 2; mt++) {
                mma_bf16(acc[mt][nt], ah[mt], bh0, bh1);
                mma_bf16(acc[mt][nt], ah[mt], bl0, bl1);
                mma_bf16(acc[mt][nt], al[mt], bh0, bh1);
            }
        }
        __syncthreads();
    }

    // epilogue: vals2[b][p*9+tap][o] = acc + vbias
    #pragma unroll
    for (int mt = 0; mt < 2; mt++) {
        int o = wm * 32 + mt * 16 + g;
        float vb0 = g_vbias[b * 576 + tap * 64 + o];
        float vb8 = g_vbias[b * 576 + tap * 64 + o + 8];
        #pragma unroll
        for (int nt = 0; nt < 8; nt++) {
            int p = pbase + wn * 64 + nt * 8 + 2 * t;
            float* d0 = g_vals2 + ((size_t)b * NPTS + (size_t)p * 9 + tap) * 64 + o;
            d0[0]       = acc[mt][nt][0] + vb0;   // pixel p,   ch o
            d0[576]     = acc[mt][nt][1] + vb0;   // pixel p+1, ch o
            d0[8]       = acc[mt][nt][2] + vb8;   // pixel p,   ch o+8
            d0[576 + 8] = acc[mt][nt][3] + vb8;   // pixel p+1, ch o+8
        }
    }
}

// ---------------- K4: build splat record table ----------------
__device__ __forceinline__ void emit_rec(int m, float wt, int yi, int xi) {
    if (yi < 0)          { yi = -yi;        xi = (xi + 512) & 1023; }
    else if (yi >= 512)  { yi = 1024 - yi;  xi = (xi + 512) & 1023; }
    if (yi > 511) yi = 511;
    if (yi < 0)   yi = 0;
    int idx = yi * 1024 + xi;
    int slot = atomicAdd(&g_cnt[idx], 1);
    if (slot < MAXREC) g_rec[(size_t)idx * MAXREC + slot] = make_int2(m, __float_as_int(wt));
}

__global__ __launch_bounds__(256) void k_build(const float* __restrict__ grid) {
    int m = blockIdx.x * 256 + threadIdx.x;
    if (m >= NPTS) return;
    float2 gxy = ((const float2*)grid)[m];
    float px = (gxy.x + 1.0f) * 0.5f * 1023.0f;
    float py = (gxy.y + 1.0f) * 0.5f * 511.0f;
    float fpx = floorf(px), fpy = floorf(py);
    int x0 = (int)fpx, y0 = (int)fpy;
    float fx = px - fpx, fy = py - fpy;
    float wx0 = 1.0f - fx, wy0 = 1.0f - fy;
    int x0w = x0 & 1023, x1w = (x0 + 1) & 1023;
    emit_rec(m, wx0 * wy0, y0,     x0w);
    emit_rec(m, wx0 * fy,  y0 + 1, x0w);
    emit_rec(m, fx  * wy0, y0,     x1w);
    emit_rec(m, fx  * fy,  y0 + 1, x1w);
}

// ---------------- K5: gather + div + bias + GN2 stats ----------------
__global__ __launch_bounds__(256) void k_gather(float* __restrict__ out) {
    int b = blockIdx.y;
    int base = blockIdx.x * 256;         // 256 pixels per block
    int tid = threadIdx.x;
    int w = tid >> 5, lane = tid & 31;
    __shared__ float buf[64][33];
    float sums[8], ssqs[8];
    #pragma unroll
    for (int r = 0; r < 8; r++) { sums[r] = 0.f; ssqs[r] = 0.f; }

    const float* vbase = g_vals2 + (size_t)b * VB;

    for (int t = 0; t < 8; t++) {
        int pb = base + t * 32;
        for (int jj = 0; jj < 4; jj++) {
            int pp = jj * 8 + w;
            int p = pb + pp;
            int cnt = g_cnt[p];
            if (cnt > MAXREC) cnt = MAXREC;
            float a0 = 0.f, a1 = 0.f, den = 0.f;
            const int2* rp = &g_rec[(size_t)p * MAXREC];
            for (int r = 0; r < cnt; r++) {
                int2 rec = rp[r];
                float wt = __int_as_float(rec.y);
                const float* v = vbase + (size_t)rec.x * 64;
                a0 += wt * v[lane];
                a1 += wt * v[lane + 32];
                den += wt;
            }
            float rd = 1.0f / fmaxf(den, 1e-8f);
            buf[lane][pp]      = a0 * rd + g_bias2[lane];
            buf[lane + 32][pp] = a1 * rd + g_bias2[lane + 32];
        }
        __syncthreads();
        #pragma unroll
        for (int r = 0; r < 8; r++) {
            int c = r * 8 + w;
            float v = buf[c][lane];
            out[((size_t)(b * 64 + c)) * HW + pb + lane] = v;
            sums[r] += v; ssqs[r] += v * v;
        }
        __syncthreads();
    }
    #pragma unroll
    for (int r = 0; r < 8; r++) {
        float s = sums[r], q = ssqs[r];
        for (int off = 16; off; off >>= 1) {
            s += __shfl_down_sync(0xffffffffu, s, off);
            q += __shfl_down_sync(0xffffffffu, q, off);
        }
        if (lane == 0) {
            atomicAdd(&g_gn2sum[b * 64 + r * 8 + w], s);
            atomicAdd(&g_gn2ssq[b * 64 + r * 8 + w], q);
        }
    }
}

// ---------------- K6: GN2 + exact GELU ----------------
__global__ __launch_bounds__(256) void k_final(float* __restrict__ out,
                                               const float* __restrict__ gamma2,
                                               const float* __restrict__ beta2) {
    size_t i4 = (size_t)blockIdx.x * 256 + threadIdx.x;   // float4 index
    int bc = (int)(i4 >> 17);            // 131072 float4 per (b,c) row
    int b = bc >> 6, c = bc & 63;
    int g = c >> 1;                      // 2 channels per group
    float S = g_gn2sum[b * 64 + 2 * g] + g_gn2sum[b * 64 + 2 * g + 1];
    float Q = g_gn2ssq[b * 64 + 2 * g] + g_gn2ssq[b * 64 + 2 * g + 1];
    float mu  = S * (1.0f / 1048576.0f);
    float var = Q * (1.0f / 1048576.0f) - mu * mu;
    float sc = rsqrtf(var + 1e-5f) * gamma2[c];
    float sh = beta2[c] - mu * sc;
    float4 v = ((float4*)out)[i4];
    float t;
    t = v.x * sc + sh; v.x = 0.5f * t * (1.0f + erff(t * 0.70710678f));
    t = v.y * sc + sh; v.y = 0.5f * t * (1.0f + erff(t * 0.70710678f));
    t = v.z * sc + sh; v.z = 0.5f * t * (1.0f + erff(t * 0.70710678f));
    t = v.w * sc + sh; v.w = 0.5f * t * (1.0f + erff(t * 0.70710678f));
    ((float4*)out)[i4] = v;
}

// ---------------- launch ----------------
extern "C" void kernel_launch(void* const* d_in, const int* in_sizes, int n_in,
                              void* d_out, int out_size) {
    const float* x          = (const float*)d_in[0];
    const float* grid       = (const float*)d_in[1];
    const float* gamma1     = (const float*)d_in[2];
    const float* beta1      = (const float*)d_in[3];
    const float* w_conv     = (const float*)d_in[4];
    const float* splat_bias = (const float*)d_in[5];
    const float* w_post     = (const float*)d_in[6];
    const float* b_post     = (const float*)d_in[7];
    const float* gamma2     = (const float*)d_in[8];
    const float* beta2      = (const float*)d_in[9];
    float* out = (float*)d_out;

    k_zero<<<2048, 256>>>();
    k_gn1<<<dim3(256, 4), 256>>>(x);
    k_split<<<32768, 256>>>(x);
    k_prep<<<576, 128>>>(w_conv, w_post, gamma1, beta1, splat_bias, b_post);
    k_gemm<<<dim3(9, 512, 2), 256>>>();
    k_build<<<4608, 256>>>(grid);
    k_gather<<<dim3(2048, 2), 256>>>(out);
    k_final<<<65536, 256>>>(out, gamma2, beta2);
}